// round 7
// baseline (speedup 1.0000x reference)
#include <cuda_runtime.h>
#include <math.h>

#define BB 64
#define CC 768
#define C2 1536
#define RR 96
#define EE 16

// ---- scratch (device globals) ----
__device__ float d_gT[CC * BB];         // pooled, [C][B]
__device__ float d_p1[12 * C2 * BB];    // gemm1 split-K partials (12 slabs)
__device__ float d_h1T[C2 * BB];        // conv1+BN+GELU, [2C][B]
__device__ float d_pa[24 * RR * BB];    // ca1 split-K partials (24 slabs)
__device__ float d_aT[RR * BB];         // bottleneck, [R][B]
__device__ float d_h2T[C2 * BB];        // gated, [2C][B]
__device__ float d_p2[24 * CC * BB];    // gemm2 split-K partials (24 slabs)
__device__ float d_h3[BB * CC];         // conv2+BN+GELU, [B][C]
__device__ unsigned long long g_cnt;    // monotonic arrival counter
__device__ volatile unsigned int g_rel; // monotonic release epoch

// smem plan (dynamic): s_act[96*64] | s_w[128*68] | s_sc[16]
#define SACT_FLOATS (96 * 64)
#define SW_FLOATS   (128 * 68)
#define SMEM_FLOATS (SACT_FLOATS + SW_FLOATS + EE)

__device__ __forceinline__ float gelu_exact(float z) {
    return 0.5f * z * (1.0f + erff(z * 0.7071067811865476f));
}
__device__ __forceinline__ float sig2(float z) {          // sigmoid(2z)
    return 1.0f / (1.0f + expf(-2.0f * z));
}

// grid barrier: atomic arrive, separate release word, monotonic (replay-safe)
__device__ __forceinline__ void gbar(int nb) {
    __syncthreads();
    if (threadIdx.x == 0) {
        __threadfence();
        unsigned long long t = atomicAdd(&g_cnt, 1ULL);
        unsigned int epoch = (unsigned int)(t / (unsigned long long)nb) + 1u;
        if ((int)(t % (unsigned long long)nb) == nb - 1) {
            g_rel = epoch;          // release
            __threadfence();
        } else {
            int spins = 0;
            while (g_rel < epoch) { if (++spins > 64) __nanosleep(64); }
            __threadfence();        // acquire
        }
    }
    __syncthreads();
}

__device__ __forceinline__ float4 unpack2(unsigned long long lo,
                                          unsigned long long hi) {
    float4 r;
    asm("mov.b64 {%0, %1}, %2;" : "=f"(r.x), "=f"(r.y) : "l"(lo));
    asm("mov.b64 {%0, %1}, %2;" : "=f"(r.z), "=f"(r.w) : "l"(hi));
    return r;
}

// fill s_w with a JT x KC weight tile (row pitch KC+4)
template<int JT, int KC>
__device__ __forceinline__ void fill_w(const float* __restrict__ W, int ldw,
                                       int j0, int k0, float* s_w) {
    const int tid = threadIdx.x;
    const float4* w4g = (const float4*)W;
    for (int f = tid; f < JT * (KC / 4); f += 256) {
        int j = f / (KC / 4), kq = f % (KC / 4);
        float4 v = w4g[((j0 + j) * ldw + k0) / 4 + kq];
        *(float4*)(s_w + j * (KC + 4) + kq * 4) = v;
    }
}

// tiled partial GEMM, packed f32x2 FMA. Thread tile TB b x TJ j.
// 256 threads: BGN = 64/TB b-groups, GJ = 256/BGN j-groups, JT = GJ*TJ.
// k-range [k0, k0+KC). act K-major [K][64]. W row-major [N][ldw].
// acc = (TB/2)*TJ packed f32x2, layout acc[q*(TB/2)+t].
template<int TB, int TJ, int KC>
__device__ __forceinline__ void tile_mm(
    const float* __restrict__ W, int ldw,
    const float* __restrict__ actT,
    int j0, int k0, bool loadw,
    unsigned long long* acc, float* s_act, float* s_w) {
    constexpr int BGN = 64 / TB;
    constexpr int GJ  = 256 / BGN;
    constexpr int JT  = GJ * TJ;
    const int tid = threadIdx.x;
    const int bg = tid % BGN, jg = tid / BGN;
    {
        const float4* a4 = (const float4*)(actT + k0 * BB);
        float4* sa4 = (float4*)s_act;
        for (int i = tid; i < KC * 16; i += 256) sa4[i] = a4[i];
    }
    if (loadw) fill_w<JT, KC>(W, ldw, j0, k0, s_w);
    __syncthreads();
    const float* aw = s_w + (jg * TJ) * (KC + 4);
#pragma unroll 4
    for (int k4 = 0; k4 < KC / 4; k4++) {
        float4 wv[TJ];
#pragma unroll
        for (int q = 0; q < TJ; q++)
            wv[q] = *(const float4*)(aw + q * (KC + 4) + k4 * 4);
#pragma unroll
        for (int u = 0; u < 4; u++) {
            int k = k4 * 4 + u;
            unsigned long long av[TB / 2];
#pragma unroll
            for (int t = 0; t < TB / 4; t++) {
                ulonglong2 p =
                    *(const ulonglong2*)(s_act + k * BB + bg * TB + t * 4);
                av[2 * t] = p.x; av[2 * t + 1] = p.y;
            }
#pragma unroll
            for (int q = 0; q < TJ; q++) {
                float w = (u == 0) ? wv[q].x : (u == 1) ? wv[q].y
                        : (u == 2) ? wv[q].z : wv[q].w;
                unsigned long long ww;
                asm("mov.b64 %0, {%1, %1};" : "=l"(ww) : "f"(w));
#pragma unroll
                for (int t = 0; t < TB / 2; t++)
                    asm("fma.rn.f32x2 %0, %1, %2, %0;"
                        : "+l"(acc[q * (TB / 2) + t]) : "l"(av[t]), "l"(ww));
            }
        }
    }
    __syncthreads();
}

__global__ __launch_bounds__(256) void fused_kernel(
    const float4* __restrict__ x,
    const float* __restrict__ w1,   const float* __restrict__ b1,
    const float* __restrict__ bn1g, const float* __restrict__ bn1b,
    const float* __restrict__ bn1m, const float* __restrict__ bn1v,
    const float* __restrict__ caw1, const float* __restrict__ cab1,
    const float* __restrict__ caw2, const float* __restrict__ cab2,
    const float* __restrict__ w2,   const float* __restrict__ b2,
    const float* __restrict__ bn2g, const float* __restrict__ bn2b,
    const float* __restrict__ bn2m, const float* __restrict__ bn2v,
    const float* __restrict__ w3,   const float* __restrict__ b3,
    float* __restrict__ out, int nb) {
    extern __shared__ float smem[];
    float* s_act = smem;
    float* s_w   = smem + SACT_FLOATS;
    float* s_sc  = smem + SACT_FLOATS + SW_FLOATS;
    const int tid = threadIdx.x;
    const int bid = blockIdx.x;

    // ---- prefetch stage-1 w1 tile into s_w (hidden under pool DRAM) ----
    if (bid < 144) fill_w<128, 64>(w1, CC, (bid % 12) * 128, (bid / 12) * 64, s_w);

    // ---- stage 0: global average pool -> gT[C][B] ----
    {
        int warp = bid * 8 + (tid >> 5);
        int lane = tid & 31;
        for (int r = warp; r < BB * CC; r += nb * 8) {
            const float4* p = x + (size_t)r * 256 + lane;
            float s = 0.f;
#pragma unroll
            for (int k = 0; k < 8; k++) {
                float4 v = p[32 * k];
                s += (v.x + v.y) + (v.z + v.w);
            }
#pragma unroll
            for (int o = 16; o; o >>= 1) s += __shfl_xor_sync(0xffffffffu, s, o);
            if (lane == 0) {
                int b = r / CC, c = r - b * CC;
                d_gT[c * BB + b] = s * (1.0f / 1024.0f);
            }
        }
    }
    gbar(nb);

    // ---- stage 1: gemm1 partials (12 jt x 12 ks = 144 items, K=768) ----
    if (bid < 144) {
        int jt = bid % 12, ks = bid / 12;
        const int bg = tid % 8, jg = tid / 8;
        unsigned long long acc[16] = {};
        tile_mm<8, 4, 64>(w1, CC, d_gT, jt * 128, ks * 64, /*loadw=*/false,
                          acc, s_act, s_w);
#pragma unroll
        for (int q = 0; q < 4; q++) {
            int j = jt * 128 + jg * 4 + q;
            float* dst = d_p1 + (ks * C2 + j) * BB + bg * 8;
            *(float4*)dst       = unpack2(acc[q * 4 + 0], acc[q * 4 + 1]);
            *(float4*)(dst + 4) = unpack2(acc[q * 4 + 2], acc[q * 4 + 3]);
        }
    }
    gbar(nb);

    // ---- stage 2: reduce 12 slabs + BN + GELU -> h1T ----
    for (int v = bid * 256 + tid; v < C2 * BB / 4; v += nb * 256) {
        float4 s = {0.f, 0.f, 0.f, 0.f};
#pragma unroll
        for (int k = 0; k < 12; k++) {
            float4 p = *((const float4*)d_p1 + k * (C2 * BB / 4) + v);
            s.x += p.x; s.y += p.y; s.z += p.z; s.w += p.w;
        }
        int j = v >> 4;
        float sc = rsqrtf(bn1v[j] + 1e-5f) * bn1g[j];
        float sh = bn1b[j] + (b1[j] - bn1m[j]) * sc;
        s.x = gelu_exact(s.x * sc + sh);
        s.y = gelu_exact(s.y * sc + sh);
        s.z = gelu_exact(s.z * sc + sh);
        s.w = gelu_exact(s.w * sc + sh);
        *((float4*)d_h1T + v) = s;
    }
    gbar(nb);

    // ---- stage 3: ca1 partials (3 jt x 24 ks = 72 items, K=1536) ----
    if (bid < 72) {
        int jt = bid % 3, ks = bid / 3;
        const int bg = tid % 8, jg = tid / 8;
        unsigned long long acc[4] = {};
        tile_mm<8, 1, 64>(caw1, C2, d_h1T, jt * 32, ks * 64, /*loadw=*/true,
                          acc, s_act, s_w);
        int j = jt * 32 + jg;
        float* dst = d_pa + (ks * RR + j) * BB + bg * 8;
        *(float4*)dst       = unpack2(acc[0], acc[1]);
        *(float4*)(dst + 4) = unpack2(acc[2], acc[3]);
    }
    gbar(nb);

    // ---- stage 4: reduce 24 slabs + GELU -> aT ----
    for (int v = bid * 256 + tid; v < RR * BB / 4; v += nb * 256) {
        float4 s = {0.f, 0.f, 0.f, 0.f};
#pragma unroll
        for (int k = 0; k < 24; k++) {
            float4 p = *((const float4*)d_pa + k * (RR * BB / 4) + v);
            s.x += p.x; s.y += p.y; s.z += p.z; s.w += p.w;
        }
        float bs = cab1[v >> 4];
        s.x = gelu_exact(s.x + bs);
        s.y = gelu_exact(s.y + bs);
        s.z = gelu_exact(s.z + bs);
        s.w = gelu_exact(s.w + bs);
        *((float4*)d_aT + v) = s;
    }
    gbar(nb);

    // ---- stage 5: ca2 (K=96) + sigmoid gating -> h2T (96 items, JT=16) ----
    if (bid < 96) {
        int j0 = bid * 16;
        const int bg = tid % 16, jg = tid / 16;
        unsigned long long acc[2] = {};
        tile_mm<4, 1, 96>(caw2, RR, d_aT, j0, 0, /*loadw=*/true,
                          acc, s_act, s_w);
        int j = j0 + jg;
        float bias = cab2[j];
        float4 z = unpack2(acc[0], acc[1]);
        float4 h = *(const float4*)(d_h1T + j * BB + bg * 4);
        float4 o;
        o.x = h.x * sig2(z.x + bias);
        o.y = h.y * sig2(z.y + bias);
        o.z = h.z * sig2(z.z + bias);
        o.w = h.w * sig2(z.w + bias);
        *(float4*)(d_h2T + j * BB + bg * 4) = o;
    }
    gbar(nb);

    // ---- stage 6: gemm2 partials (6 jt x 24 ks = 144 items, K=1536) ----
    if (bid < 144) {
        int jt = bid % 6, ks = bid / 6;
        const int bg = tid % 8, jg = tid / 8;
        unsigned long long acc[16] = {};
        tile_mm<8, 4, 64>(w2, C2, d_h2T, jt * 128, ks * 64, /*loadw=*/true,
                          acc, s_act, s_w);
#pragma unroll
        for (int q = 0; q < 4; q++) {
            int j = jt * 128 + jg * 4 + q;
            float* dst = d_p2 + (ks * CC + j) * BB + bg * 8;
            *(float4*)dst       = unpack2(acc[q * 4 + 0], acc[q * 4 + 1]);
            *(float4*)(dst + 4) = unpack2(acc[q * 4 + 2], acc[q * 4 + 3]);
        }
    }
    gbar(nb);

    // ---- stage 7: reduce 24 slabs + BN + GELU -> h3 [B][C] ----
    for (int v = bid * 256 + tid; v < CC * BB / 4; v += nb * 256) {
        float4 s = {0.f, 0.f, 0.f, 0.f};
#pragma unroll
        for (int k = 0; k < 24; k++) {
            float4 p = *((const float4*)d_p2 + k * (CC * BB / 4) + v);
            s.x += p.x; s.y += p.y; s.z += p.z; s.w += p.w;
        }
        int j = v >> 4, b0 = (v & 15) * 4;
        float sc = rsqrtf(bn2v[j] + 1e-5f) * bn2g[j];
        float sh = bn2b[j] + (b2[j] - bn2m[j]) * sc;
        d_h3[(b0 + 0) * CC + j] = gelu_exact(s.x * sc + sh);
        d_h3[(b0 + 1) * CC + j] = gelu_exact(s.y * sc + sh);
        d_h3[(b0 + 2) * CC + j] = gelu_exact(s.z * sc + sh);
        d_h3[(b0 + 3) * CC + j] = gelu_exact(s.w * sc + sh);
    }
    gbar(nb);

    // ---- stage 8: scores + top-2 + softmax ----
    if (bid < BB) {
        int b = bid;
        int w = tid >> 5, lane = tid & 31;
        const float* h = d_h3 + b * CC;
#pragma unroll
        for (int q = 0; q < 2; q++) {
            int e = w + 8 * q;
            const float* wr = w3 + e * CC;
            float s = 0.f;
#pragma unroll
            for (int i = 0; i < CC / 32; i++) {
                int k = lane + 32 * i;
                s = fmaf(h[k], wr[k], s);
            }
#pragma unroll
            for (int o = 16; o; o >>= 1) s += __shfl_xor_sync(0xffffffffu, s, o);
            if (lane == 0) s_sc[e] = s + b3[e];
        }
        __syncthreads();
        if (tid == 0) {
            int i0 = 0; float v0 = s_sc[0];
#pragma unroll
            for (int t = 1; t < EE; t++) { if (s_sc[t] > v0) { v0 = s_sc[t]; i0 = t; } }
            int i1 = -1; float v1 = -3.402823466e38f;
#pragma unroll
            for (int t = 0; t < EE; t++) {
                if (t != i0 && s_sc[t] > v1) { v1 = s_sc[t]; i1 = t; }
            }
            float e1  = expf((v1 - v0) * 0.5f);
            float inv = 1.0f / (1.0f + e1);
            out[b * 2 + 0]       = (float)i0;
            out[b * 2 + 1]       = (float)i1;
            out[128 + b * 2 + 0] = inv;
            out[128 + b * 2 + 1] = e1 * inv;
        }
    }
}

extern "C" void kernel_launch(void* const* d_in, const int* in_sizes, int n_in,
                              void* d_out, int out_size) {
    const float* x     = (const float*)d_in[0];
    const float* w1    = (const float*)d_in[1];
    const float* b1    = (const float*)d_in[2];
    const float* bn1_g = (const float*)d_in[3];
    const float* bn1_b = (const float*)d_in[4];
    const float* bn1_m = (const float*)d_in[5];
    const float* bn1_v = (const float*)d_in[6];
    const float* caw1  = (const float*)d_in[7];
    const float* cab1  = (const float*)d_in[8];
    const float* caw2  = (const float*)d_in[9];
    const float* cab2  = (const float*)d_in[10];
    const float* w2    = (const float*)d_in[11];
    const float* b2    = (const float*)d_in[12];
    const float* bn2_g = (const float*)d_in[13];
    const float* bn2_b = (const float*)d_in[14];
    const float* bn2_m = (const float*)d_in[15];
    const float* bn2_v = (const float*)d_in[16];
    const float* w3    = (const float*)d_in[17];
    const float* b3    = (const float*)d_in[18];

    int nsm = 148;
    cudaDeviceGetAttribute(&nsm, cudaDevAttrMultiProcessorCount, 0);
    int nb = 2 * nsm;  // 2 co-resident blocks per SM

    size_t smem_bytes = SMEM_FLOATS * sizeof(float);  // ~60 KB
    cudaFuncSetAttribute(fused_kernel,
                         cudaFuncAttributeMaxDynamicSharedMemorySize,
                         (int)smem_bytes);

    fused_kernel<<<nb, 256, smem_bytes>>>((const float4*)x,
        w1, b1, bn1_g, bn1_b, bn1_m, bn1_v,
        caw1, cab1, caw2, cab2,
        w2, b2, bn2_g, bn2_b, bn2_m, bn2_v,
        w3, b3, (float*)d_out, nb);
}

// round 8
// speedup vs baseline: 1.2195x; 1.2195x over previous
#include <cuda_runtime.h>
#include <math.h>

#define BB 64
#define CC 768
#define C2 1536
#define RR 96
#define EE 16

// ---- scratch (device globals) ----
__device__ float d_gT[CC * BB];         // pooled, [C][B]
__device__ float d_p1[24 * C2 * BB];    // gemm1 split-K partials (24 slabs)
__device__ float d_h1T[C2 * BB];        // conv1+BN+GELU, [2C][B]
__device__ float d_pa[48 * RR * BB];    // ca1 split-K partials (48 slabs)
__device__ float d_aT[RR * BB];         // bottleneck, [R][B]
__device__ float d_h2T[C2 * BB];        // gated, [2C][B]
__device__ float d_p2[48 * CC * BB];    // gemm2 split-K partials (48 slabs)
__device__ float d_h3[BB * CC];         // conv2+BN+GELU, [B][C]
__device__ unsigned long long g_cnt;    // monotonic arrival counter
__device__ volatile unsigned int g_rel; // monotonic release epoch

__device__ __forceinline__ float gelu_exact(float z) {
    return 0.5f * z * (1.0f + erff(z * 0.7071067811865476f));
}
__device__ __forceinline__ float sig2(float z) {          // sigmoid(2z)
    return 1.0f / (1.0f + expf(-2.0f * z));
}

// grid barrier: atomic arrive, separate release word, monotonic (replay-safe)
__device__ __forceinline__ void gbar(int nb) {
    __syncthreads();
    if (threadIdx.x == 0) {
        __threadfence();
        unsigned long long t = atomicAdd(&g_cnt, 1ULL);
        unsigned int epoch = (unsigned int)(t / (unsigned long long)nb) + 1u;
        if ((int)(t % (unsigned long long)nb) == nb - 1) {
            g_rel = epoch;          // release
            __threadfence();
        } else {
            int spins = 0;
            while (g_rel < epoch) { if (++spins > 64) __nanosleep(64); }
            __threadfence();        // acquire
        }
    }
    __syncthreads();
}

__device__ __forceinline__ float4 unpack2(unsigned long long lo,
                                          unsigned long long hi) {
    float4 r;
    asm("mov.b64 {%0, %1}, %2;" : "=f"(r.x), "=f"(r.y) : "l"(lo));
    asm("mov.b64 {%0, %1}, %2;" : "=f"(r.z), "=f"(r.w) : "l"(hi));
    return r;
}

// fill s_w with a JT x KC weight tile (row pitch KC+4)
template<int JT, int KC>
__device__ __forceinline__ void fill_w(const float* __restrict__ W, int ldw,
                                       int j0, int k0, float* s_w) {
    const int tid = threadIdx.x;
    const float4* w4g = (const float4*)W;
    for (int f = tid; f < JT * (KC / 4); f += 256) {
        int j = f / (KC / 4), kq = f % (KC / 4);
        float4 v = w4g[((j0 + j) * ldw + k0) / 4 + kq];
        *(float4*)(s_w + j * (KC + 4) + kq * 4) = v;
    }
}

// tiled partial GEMM, packed f32x2 FMA. Thread tile TB b x TJ j.
// 256 threads: BGN = 64/TB b-groups, GJ = 256/BGN j-groups, JT = GJ*TJ.
// k-range [k0, k0+KC). act K-major [K][64]. W row-major [N][ldw].
// acc = (TB/2)*TJ packed f32x2, layout acc[q*(TB/2)+t].
template<int TB, int TJ, int KC>
__device__ __forceinline__ void tile_mm(
    const float* __restrict__ W, int ldw,
    const float* __restrict__ actT,
    int j0, int k0, bool loadw,
    unsigned long long* acc, float* s_act, float* s_w) {
    constexpr int BGN = 64 / TB;
    constexpr int GJ  = 256 / BGN;
    constexpr int JT  = GJ * TJ;
    const int tid = threadIdx.x;
    const int bg = tid % BGN, jg = tid / BGN;
    {
        const float4* a4 = (const float4*)(actT + k0 * BB);
        float4* sa4 = (float4*)s_act;
        for (int i = tid; i < KC * 16; i += 256) sa4[i] = a4[i];
    }
    if (loadw) fill_w<JT, KC>(W, ldw, j0, k0, s_w);
    __syncthreads();
    const float* aw = s_w + (jg * TJ) * (KC + 4);
#pragma unroll 4
    for (int k4 = 0; k4 < KC / 4; k4++) {
        float4 wv[TJ];
#pragma unroll
        for (int q = 0; q < TJ; q++)
            wv[q] = *(const float4*)(aw + q * (KC + 4) + k4 * 4);
#pragma unroll
        for (int u = 0; u < 4; u++) {
            int k = k4 * 4 + u;
            unsigned long long av[TB / 2];
#pragma unroll
            for (int t = 0; t < TB / 4; t++) {
                ulonglong2 p =
                    *(const ulonglong2*)(s_act + k * BB + bg * TB + t * 4);
                av[2 * t] = p.x; av[2 * t + 1] = p.y;
            }
#pragma unroll
            for (int q = 0; q < TJ; q++) {
                float w = (u == 0) ? wv[q].x : (u == 1) ? wv[q].y
                        : (u == 2) ? wv[q].z : wv[q].w;
                unsigned long long ww;
                asm("mov.b64 %0, {%1, %1};" : "=l"(ww) : "f"(w));
#pragma unroll
                for (int t = 0; t < TB / 2; t++)
                    asm("fma.rn.f32x2 %0, %1, %2, %0;"
                        : "+l"(acc[q * (TB / 2) + t]) : "l"(av[t]), "l"(ww));
            }
        }
    }
    __syncthreads();
}

__global__ __launch_bounds__(256, 4) void fused_kernel(
    const float4* __restrict__ x,
    const float* __restrict__ w1,   const float* __restrict__ b1,
    const float* __restrict__ bn1g, const float* __restrict__ bn1b,
    const float* __restrict__ bn1m, const float* __restrict__ bn1v,
    const float* __restrict__ caw1, const float* __restrict__ cab1,
    const float* __restrict__ caw2, const float* __restrict__ cab2,
    const float* __restrict__ w2,   const float* __restrict__ b2,
    const float* __restrict__ bn2g, const float* __restrict__ bn2b,
    const float* __restrict__ bn2m, const float* __restrict__ bn2v,
    const float* __restrict__ w3,   const float* __restrict__ b3,
    float* __restrict__ out, int nb) {
    __shared__ float s_act[96 * 64];    // 24 KB (ca2 uses 96 rows; others 32)
    __shared__ float s_w[64 * 36];      // 9 KB  (max JT*(KC+4))
    __shared__ float s_sc[EE];
    const int tid = threadIdx.x;
    const int bid = blockIdx.x;

    // ---- prefetch stage-1 w1 tile into s_w (hidden under pool DRAM) ----
    if (bid < 576) fill_w<64, 32>(w1, CC, (bid % 24) * 64, (bid / 24) * 32, s_w);

    // ---- stage 0: global average pool -> gT[C][B] ----
    {
        int warp = bid * 8 + (tid >> 5);
        int lane = tid & 31;
        for (int r = warp; r < BB * CC; r += nb * 8) {
            const float4* p = x + (size_t)r * 256 + lane;
            float s = 0.f;
#pragma unroll
            for (int k = 0; k < 8; k++) {
                float4 v = p[32 * k];
                s += (v.x + v.y) + (v.z + v.w);
            }
#pragma unroll
            for (int o = 16; o; o >>= 1) s += __shfl_xor_sync(0xffffffffu, s, o);
            if (lane == 0) {
                int b = r / CC, c = r - b * CC;
                d_gT[c * BB + b] = s * (1.0f / 1024.0f);
            }
        }
    }
    gbar(nb);

    // ---- stage 1: gemm1 partials (24 jt x 24 ks = 576 items, K=768) ----
    if (bid < 576) {
        int jt = bid % 24, ks = bid / 24;
        const int bg = tid % 16, jg = tid / 16;
        unsigned long long acc[8] = {};
        tile_mm<4, 4, 32>(w1, CC, d_gT, jt * 64, ks * 32, /*loadw=*/false,
                          acc, s_act, s_w);
#pragma unroll
        for (int q = 0; q < 4; q++) {
            int j = jt * 64 + jg * 4 + q;
            *(float4*)(d_p1 + (ks * C2 + j) * BB + bg * 4) =
                unpack2(acc[q * 2 + 0], acc[q * 2 + 1]);
        }
    }
    gbar(nb);

    // ---- stage 2: reduce 24 slabs + BN + GELU -> h1T ----
    for (int v = bid * 256 + tid; v < C2 * BB / 4; v += nb * 256) {
        float4 s = {0.f, 0.f, 0.f, 0.f};
#pragma unroll
        for (int k = 0; k < 24; k++) {
            float4 p = *((const float4*)d_p1 + k * (C2 * BB / 4) + v);
            s.x += p.x; s.y += p.y; s.z += p.z; s.w += p.w;
        }
        int j = v >> 4;
        float sc = rsqrtf(bn1v[j] + 1e-5f) * bn1g[j];
        float sh = bn1b[j] + (b1[j] - bn1m[j]) * sc;
        s.x = gelu_exact(s.x * sc + sh);
        s.y = gelu_exact(s.y * sc + sh);
        s.z = gelu_exact(s.z * sc + sh);
        s.w = gelu_exact(s.w * sc + sh);
        *((float4*)d_h1T + v) = s;
    }
    gbar(nb);

    // ---- stage 3: ca1 partials (3 jt x 48 ks = 144 items, K=1536) ----
    if (bid < 144) {
        int jt = bid % 3, ks = bid / 3;
        const int bg = tid % 8, jg = tid / 8;
        unsigned long long acc[4] = {};
        tile_mm<8, 1, 32>(caw1, C2, d_h1T, jt * 32, ks * 32, /*loadw=*/true,
                          acc, s_act, s_w);
        int j = jt * 32 + jg;
        float* dst = d_pa + (ks * RR + j) * BB + bg * 8;
        *(float4*)dst       = unpack2(acc[0], acc[1]);
        *(float4*)(dst + 4) = unpack2(acc[2], acc[3]);
    }
    gbar(nb);

    // ---- stage 4: reduce 48 slabs + GELU -> aT ----
    for (int v = bid * 256 + tid; v < RR * BB / 4; v += nb * 256) {
        float4 s = {0.f, 0.f, 0.f, 0.f};
#pragma unroll
        for (int k = 0; k < 48; k++) {
            float4 p = *((const float4*)d_pa + k * (RR * BB / 4) + v);
            s.x += p.x; s.y += p.y; s.z += p.z; s.w += p.w;
        }
        float bs = cab1[v >> 4];
        s.x = gelu_exact(s.x + bs);
        s.y = gelu_exact(s.y + bs);
        s.z = gelu_exact(s.z + bs);
        s.w = gelu_exact(s.w + bs);
        *((float4*)d_aT + v) = s;
    }
    gbar(nb);

    // ---- stage 5: ca2 (K=96) + sigmoid gating -> h2T (96 items, JT=16) ----
    if (bid < 96) {
        int j0 = bid * 16;
        const int bg = tid % 16, jg = tid / 16;
        unsigned long long acc[2] = {};
        tile_mm<4, 1, 96>(caw2, RR, d_aT, j0, 0, /*loadw=*/true,
                          acc, s_act, s_w);
        int j = j0 + jg;
        float bias = cab2[j];
        float4 z = unpack2(acc[0], acc[1]);
        float4 h = *(const float4*)(d_h1T + j * BB + bg * 4);
        float4 o;
        o.x = h.x * sig2(z.x + bias);
        o.y = h.y * sig2(z.y + bias);
        o.z = h.z * sig2(z.z + bias);
        o.w = h.w * sig2(z.w + bias);
        *(float4*)(d_h2T + j * BB + bg * 4) = o;
    }
    gbar(nb);

    // ---- stage 6: gemm2 partials (12 jt x 48 ks = 576 items, K=1536) ----
    if (bid < 576) {
        int jt = bid % 12, ks = bid / 12;
        const int bg = tid % 16, jg = tid / 16;
        unsigned long long acc[8] = {};
        tile_mm<4, 4, 32>(w2, C2, d_h2T, jt * 64, ks * 32, /*loadw=*/true,
                          acc, s_act, s_w);
#pragma unroll
        for (int q = 0; q < 4; q++) {
            int j = jt * 64 + jg * 4 + q;
            *(float4*)(d_p2 + (ks * CC + j) * BB + bg * 4) =
                unpack2(acc[q * 2 + 0], acc[q * 2 + 1]);
        }
    }
    gbar(nb);

    // ---- stage 7: reduce 48 slabs + BN + GELU -> h3 [B][C] ----
    for (int v = bid * 256 + tid; v < CC * BB / 4; v += nb * 256) {
        float4 s = {0.f, 0.f, 0.f, 0.f};
#pragma unroll
        for (int k = 0; k < 48; k++) {
            float4 p = *((const float4*)d_p2 + k * (CC * BB / 4) + v);
            s.x += p.x; s.y += p.y; s.z += p.z; s.w += p.w;
        }
        int j = v >> 4, b0 = (v & 15) * 4;
        float sc = rsqrtf(bn2v[j] + 1e-5f) * bn2g[j];
        float sh = bn2b[j] + (b2[j] - bn2m[j]) * sc;
        d_h3[(b0 + 0) * CC + j] = gelu_exact(s.x * sc + sh);
        d_h3[(b0 + 1) * CC + j] = gelu_exact(s.y * sc + sh);
        d_h3[(b0 + 2) * CC + j] = gelu_exact(s.z * sc + sh);
        d_h3[(b0 + 3) * CC + j] = gelu_exact(s.w * sc + sh);
    }
    gbar(nb);

    // ---- stage 8: scores + top-2 + softmax ----
    if (bid < BB) {
        int b = bid;
        int w = tid >> 5, lane = tid & 31;
        const float* h = d_h3 + b * CC;
#pragma unroll
        for (int q = 0; q < 2; q++) {
            int e = w + 8 * q;
            const float* wr = w3 + e * CC;
            float s = 0.f;
#pragma unroll
            for (int i = 0; i < CC / 32; i++) {
                int k = lane + 32 * i;
                s = fmaf(h[k], wr[k], s);
            }
#pragma unroll
            for (int o = 16; o; o >>= 1) s += __shfl_xor_sync(0xffffffffu, s, o);
            if (lane == 0) s_sc[e] = s + b3[e];
        }
        __syncthreads();
        if (tid == 0) {
            int i0 = 0; float v0 = s_sc[0];
#pragma unroll
            for (int t = 1; t < EE; t++) { if (s_sc[t] > v0) { v0 = s_sc[t]; i0 = t; } }
            int i1 = -1; float v1 = -3.402823466e38f;
#pragma unroll
            for (int t = 0; t < EE; t++) {
                if (t != i0 && s_sc[t] > v1) { v1 = s_sc[t]; i1 = t; }
            }
            float e1  = expf((v1 - v0) * 0.5f);
            float inv = 1.0f / (1.0f + e1);
            out[b * 2 + 0]       = (float)i0;
            out[b * 2 + 1]       = (float)i1;
            out[128 + b * 2 + 0] = inv;
            out[128 + b * 2 + 1] = e1 * inv;
        }
    }
}

extern "C" void kernel_launch(void* const* d_in, const int* in_sizes, int n_in,
                              void* d_out, int out_size) {
    const float* x     = (const float*)d_in[0];
    const float* w1    = (const float*)d_in[1];
    const float* b1    = (const float*)d_in[2];
    const float* bn1_g = (const float*)d_in[3];
    const float* bn1_b = (const float*)d_in[4];
    const float* bn1_m = (const float*)d_in[5];
    const float* bn1_v = (const float*)d_in[6];
    const float* caw1  = (const float*)d_in[7];
    const float* cab1  = (const float*)d_in[8];
    const float* caw2  = (const float*)d_in[9];
    const float* cab2  = (const float*)d_in[10];
    const float* w2    = (const float*)d_in[11];
    const float* b2    = (const float*)d_in[12];
    const float* bn2_g = (const float*)d_in[13];
    const float* bn2_b = (const float*)d_in[14];
    const float* bn2_m = (const float*)d_in[15];
    const float* bn2_v = (const float*)d_in[16];
    const float* w3    = (const float*)d_in[17];
    const float* b3    = (const float*)d_in[18];

    int nsm = 148;
    cudaDeviceGetAttribute(&nsm, cudaDevAttrMultiProcessorCount, 0);
    int nb = 4 * nsm;  // 4 co-resident blocks per SM (33 KB smem, 64 regs)

    fused_kernel<<<nb, 256>>>((const float4*)x,
        w1, b1, bn1_g, bn1_b, bn1_m, bn1_v,
        caw1, cab1, caw2, cab2,
        w2, b2, bn2_g, bn2_b, bn2_m, bn2_v,
        w3, b3, (float*)d_out, nb);
}